// round 8
// baseline (speedup 1.0000x reference)
#include <cuda_runtime.h>
#include <cstdint>

#define BATCH 8
#define NNODES 50000
#define DIM 64
#define ROW_F4 16
#define TOTAL_ROWS ((size_t)BATCH * NNODES)   // 400000
#define MAX_E 1600000

__device__ int g_is64;
__device__ int g_row_start[NNODES + 1];
__device__ int g_cursor[NNODES];
__device__ int g_col[MAX_E];

// ---------------------------------------------------------------------------
// packed f32x2 helpers
// ---------------------------------------------------------------------------
__device__ __forceinline__ unsigned long long pack2(float a, float b) {
    unsigned long long r;
    asm("mov.b64 %0, {%1, %2};" : "=l"(r) : "f"(a), "f"(b));
    return r;
}
__device__ __forceinline__ unsigned long long fma2(unsigned long long a,
                                                   unsigned long long b,
                                                   unsigned long long c) {
    unsigned long long d;
    asm("fma.rn.f32x2 %0, %1, %2, %3;" : "=l"(d) : "l"(a), "l"(b), "l"(c));
    return d;
}
__device__ __forceinline__ void unpack2(unsigned long long v, float& lo, float& hi) {
    asm("mov.b64 {%0, %1}, %2;" : "=f"(lo), "=f"(hi) : "l"(v));
}

__device__ __forceinline__ int edge_count(int is64, int nwords) {
    if (is64) return (nwords >= 3000000) ? (nwords >> 2) : (nwords >> 1);
    return nwords >> 1;
}
__device__ __forceinline__ void load_edge(const void* raw, int is64, int e,
                                          int& s, int& d) {
    if (is64) {
        const long long* p = (const long long*)raw;
        s = (int)p[2 * (long long)e];
        d = (int)p[2 * (long long)e + 1];
    } else {
        const int* p = (const int*)raw;
        s = p[2 * e];
        d = p[2 * e + 1];
    }
}

// ---------------------------------------------------------------------------
// Kernel 0: detect edge dtype + zero the per-node counters
// ---------------------------------------------------------------------------
__global__ void detect_dtype_kernel(const int* __restrict__ w, int nwords) {
    __shared__ int any_nonzero;
    if (threadIdx.x == 0) any_nonzero = 0;
    __syncthreads();
    int limit = nwords / 2;
    if (limit > 16384) limit = 16384;
    for (int i = threadIdx.x; i < limit; i += blockDim.x) {
        if (w[2 * i + 1] != 0) any_nonzero = 1;
    }
    __syncthreads();
    if (threadIdx.x == 0) g_is64 = (any_nonzero == 0) ? 1 : 0;
    for (int i = threadIdx.x; i < NNODES; i += blockDim.x) g_cursor[i] = 0;
}

// ---------------------------------------------------------------------------
// Kernel 1: per-dst degree histogram
// ---------------------------------------------------------------------------
__global__ void count_kernel(const void* __restrict__ edges, int nwords) {
    int is64 = g_is64;
    int n = edge_count(is64, nwords);
    int e = blockIdx.x * blockDim.x + threadIdx.x;
    if (e >= n) return;
    int s, d;
    load_edge(edges, is64, e, s, d);
    atomicAdd(&g_cursor[d], 1);
}

// ---------------------------------------------------------------------------
// Kernel 2: exclusive scan of degrees -> row_start; reset cursors
// ---------------------------------------------------------------------------
__global__ void scan_kernel() {
    __shared__ int part[1024];
    int t = threadIdx.x;
    const int chunk = (NNODES + 1023) / 1024;   // 49
    int begin = t * chunk;
    int end = begin + chunk;
    if (end > NNODES) end = NNODES;
    int s = 0;
    for (int i = begin; i < end; i++) s += g_cursor[i];
    part[t] = s;
    __syncthreads();
    for (int off = 1; off < 1024; off <<= 1) {
        int v = (t >= off) ? part[t - off] : 0;
        __syncthreads();
        part[t] += v;
        __syncthreads();
    }
    int offset = (t > 0) ? part[t - 1] : 0;
    for (int i = begin; i < end; i++) {
        int c = g_cursor[i];
        g_row_start[i] = offset;
        offset += c;
        g_cursor[i] = 0;
    }
    if (t == 1023) g_row_start[NNODES] = part[1023];
}

// ---------------------------------------------------------------------------
// Kernel 3: fill CSR column (src) lists
// ---------------------------------------------------------------------------
__global__ void fill_kernel(const void* __restrict__ edges, int nwords) {
    int is64 = g_is64;
    int n = edge_count(is64, nwords);
    int e = blockIdx.x * blockDim.x + threadIdx.x;
    if (e >= n) return;
    int s, d;
    load_edge(edges, is64, e, s, d);
    int pos = g_row_start[d] + atomicAdd(&g_cursor[d], 1);
    g_col[pos] = s;
}

// ---------------------------------------------------------------------------
// Kernel 4: fused gather + dual-GEMM + bias + ReLU.
// Block = 256 threads (8 warps), 128 rows.
//  Phase A: stage x-tile (coalesced) + weights [k][o] into smem.
//  Phase B: gather — warp w computes agg for rows [16w,16w+16): for each row,
//           lane owns floats {2*lane, 2*lane+1}; iterate in-edges (4-way
//           unrolled, 4 independent accumulators -> MLP=4), write sA.
//  Phase C: R5 GEMM — half-warp h = row parity, lane-in-half i owns outputs
//           4i..4i+3 as f32x2 pairs; row data via broadcast LDS; weights
//           register-cached per 4-k chunk.
// ---------------------------------------------------------------------------
#define WSTRIDE 68
#define SX_OFF 0
#define SA_OFF (128 * 64)
#define SWS_OFF (2 * 128 * 64)
#define SWN_OFF (SWS_OFF + 64 * WSTRIDE)
#define SB_OFF (SWN_OFF + 64 * WSTRIDE)
#define SMEM_FLOATS (SB_OFF + 64)

__global__ __launch_bounds__(256) void fused_gnn_kernel(
        const float* __restrict__ x,
        const float* __restrict__ Ws, const float* __restrict__ bs,
        const float* __restrict__ Wn, const float* __restrict__ bn,
        float* __restrict__ out) {
    extern __shared__ float sm[];
    float* sX = sm + SX_OFF;
    float* sA = sm + SA_OFF;
    float* sWs = sm + SWS_OFF;
    float* sWn = sm + SWN_OFF;
    float* sb = sm + SB_OFF;

    int tid = threadIdx.x;
    int warp = tid >> 5;
    int lane = tid & 31;
    size_t rowbase = (size_t)blockIdx.x * 128;

    // --- Phase A: stage x rows + weights ---
    {
        const float4* xg = reinterpret_cast<const float4*>(x + rowbase * DIM);
        float4* sx4 = reinterpret_cast<float4*>(sX);
#pragma unroll
        for (int t = 0; t < 8; t++) {
            int idx = tid + t * 256;
            sx4[idx] = xg[idx];
        }
    }
    for (int idx = tid; idx < DIM * DIM; idx += 256) {
        int o = idx >> 6;
        int k = idx & 63;
        sWs[k * WSTRIDE + o] = Ws[idx];
        sWn[k * WSTRIDE + o] = Wn[idx];
    }
    if (tid < DIM) sb[tid] = bs[tid] + bn[tid];

    // --- Phase B: gather agg rows into sA ---
#pragma unroll 1
    for (int rr = 0; rr < 16; rr++) {
        int rl = warp * 16 + rr;
        size_t row = rowbase + (size_t)rl;
        int b = (int)(row / NNODES);
        int node = (int)(row % NNODES);
        int start = g_row_start[node];
        int end = g_row_start[node + 1];
        const float* xb = x + (size_t)b * NNODES * DIM;

        float2 a0 = {0.f, 0.f}, a1 = {0.f, 0.f}, a2 = {0.f, 0.f}, a3 = {0.f, 0.f};
        for (int e0 = start; e0 < end; e0 += 32) {
            int cnt = end - e0;
            if (cnt > 32) cnt = 32;
            int my = (lane < cnt) ? g_col[e0 + lane] : 0;
            int t = 0;
            for (; t + 4 <= cnt; t += 4) {
                int s0 = __shfl_sync(0xffffffffu, my, t);
                int s1 = __shfl_sync(0xffffffffu, my, t + 1);
                int s2 = __shfl_sync(0xffffffffu, my, t + 2);
                int s3 = __shfl_sync(0xffffffffu, my, t + 3);
                float2 v0 = *reinterpret_cast<const float2*>(xb + (size_t)s0 * DIM + 2 * lane);
                float2 v1 = *reinterpret_cast<const float2*>(xb + (size_t)s1 * DIM + 2 * lane);
                float2 v2 = *reinterpret_cast<const float2*>(xb + (size_t)s2 * DIM + 2 * lane);
                float2 v3 = *reinterpret_cast<const float2*>(xb + (size_t)s3 * DIM + 2 * lane);
                a0.x += v0.x; a0.y += v0.y;
                a1.x += v1.x; a1.y += v1.y;
                a2.x += v2.x; a2.y += v2.y;
                a3.x += v3.x; a3.y += v3.y;
            }
            for (; t < cnt; t++) {
                int s0 = __shfl_sync(0xffffffffu, my, t);
                float2 v0 = *reinterpret_cast<const float2*>(xb + (size_t)s0 * DIM + 2 * lane);
                a0.x += v0.x; a0.y += v0.y;
            }
        }
        float2 s;
        s.x = (a0.x + a1.x) + (a2.x + a3.x);
        s.y = (a0.y + a1.y) + (a2.y + a3.y);
        *reinterpret_cast<float2*>(&sA[rl * DIM + 2 * lane]) = s;
    }
    __syncthreads();

    // --- Phase C: GEMM + bias + relu ---
    int h = lane >> 4;
    int i = lane & 15;

    unsigned long long bias0 = pack2(sb[4 * i], sb[4 * i + 1]);
    unsigned long long bias1 = pack2(sb[4 * i + 2], sb[4 * i + 3]);
    unsigned long long acc[8][2];
#pragma unroll
    for (int j = 0; j < 8; j++) { acc[j][0] = bias0; acc[j][1] = bias1; }

    int row0 = warp * 16 + h;

#pragma unroll 1
    for (int c = 0; c < 16; c++) {
        int k0 = c * 4;
        unsigned long long wsv[4][2], wnv[4][2];
#pragma unroll
        for (int k = 0; k < 4; k++) {
            float4 w = *reinterpret_cast<const float4*>(&sWs[(k0 + k) * WSTRIDE + 4 * i]);
            wsv[k][0] = pack2(w.x, w.y);
            wsv[k][1] = pack2(w.z, w.w);
            float4 u = *reinterpret_cast<const float4*>(&sWn[(k0 + k) * WSTRIDE + 4 * i]);
            wnv[k][0] = pack2(u.x, u.y);
            wnv[k][1] = pack2(u.z, u.w);
        }
#pragma unroll
        for (int j = 0; j < 8; j++) {
            int r = row0 + 2 * j;
            float4 xv = *reinterpret_cast<const float4*>(&sX[r * DIM + k0]);
            float4 av = *reinterpret_cast<const float4*>(&sA[r * DIM + k0]);
            float xe[4] = {xv.x, xv.y, xv.z, xv.w};
            float ae[4] = {av.x, av.y, av.z, av.w};
#pragma unroll
            for (int k = 0; k < 4; k++) {
                unsigned long long xp = pack2(xe[k], xe[k]);
                unsigned long long ap = pack2(ae[k], ae[k]);
                acc[j][0] = fma2(xp, wsv[k][0], acc[j][0]);
                acc[j][0] = fma2(ap, wnv[k][0], acc[j][0]);
                acc[j][1] = fma2(xp, wsv[k][1], acc[j][1]);
                acc[j][1] = fma2(ap, wnv[k][1], acc[j][1]);
            }
        }
    }

#pragma unroll
    for (int j = 0; j < 8; j++) {
        size_t row = rowbase + (size_t)(row0 + 2 * j);
        float l0, h0, l1, h1;
        unpack2(acc[j][0], l0, h0);
        unpack2(acc[j][1], l1, h1);
        float4 r;
        r.x = fmaxf(l0, 0.f);
        r.y = fmaxf(h0, 0.f);
        r.z = fmaxf(l1, 0.f);
        r.w = fmaxf(h1, 0.f);
        *reinterpret_cast<float4*>(out + row * DIM + 4 * i) = r;
    }
}

// ---------------------------------------------------------------------------
// Launch
// ---------------------------------------------------------------------------
extern "C" void kernel_launch(void* const* d_in, const int* in_sizes, int n_in,
                              void* d_out, int out_size) {
    const float* x = (const float*)d_in[0];
    const void* edges = d_in[1];
    const float* Ws = (const float*)d_in[2];
    const float* bs = (const float*)d_in[3];
    const float* Wn = (const float*)d_in[4];
    const float* bn = (const float*)d_in[5];
    float* out = (float*)d_out;

    int nwords = in_sizes[1];
    int max_edges = nwords / 2;
    int eblocks = (max_edges + 255) / 256;

    // CSR build
    detect_dtype_kernel<<<1, 256>>>((const int*)edges, nwords);
    count_kernel<<<eblocks, 256>>>(edges, nwords);
    scan_kernel<<<1, 1024>>>();
    fill_kernel<<<eblocks, 256>>>(edges, nwords);

    // fused gather + dual-GEMM + relu
    int smem_bytes = SMEM_FLOATS * (int)sizeof(float);
    cudaFuncSetAttribute(fused_gnn_kernel,
                         cudaFuncAttributeMaxDynamicSharedMemorySize, smem_bytes);
    int gblocks = (int)(TOTAL_ROWS / 128);   // 3125
    fused_gnn_kernel<<<gblocks, 256, smem_bytes>>>(x, Ws, bs, Wn, bn, out);
}

// round 10
// speedup vs baseline: 1.1578x; 1.1578x over previous
#include <cuda_runtime.h>
#include <cstdint>

#define BATCH 8
#define NNODES 50000
#define DIM 64
#define ROW_F4 16
#define TOTAL_ROWS ((size_t)BATCH * NNODES)   // 400000
#define MAX_E 1600000

__device__ int g_is64;
__device__ int g_row_start[NNODES + 1];
__device__ int g_cursor[NNODES];
__device__ int g_col[MAX_E];

// ---------------------------------------------------------------------------
// packed f32x2 helpers
// ---------------------------------------------------------------------------
__device__ __forceinline__ unsigned long long pack2(float a, float b) {
    unsigned long long r;
    asm("mov.b64 %0, {%1, %2};" : "=l"(r) : "f"(a), "f"(b));
    return r;
}
__device__ __forceinline__ unsigned long long fma2(unsigned long long a,
                                                   unsigned long long b,
                                                   unsigned long long c) {
    unsigned long long d;
    asm("fma.rn.f32x2 %0, %1, %2, %3;" : "=l"(d) : "l"(a), "l"(b), "l"(c));
    return d;
}
__device__ __forceinline__ void unpack2(unsigned long long v, float& lo, float& hi) {
    asm("mov.b64 {%0, %1}, %2;" : "=f"(lo), "=f"(hi) : "l"(v));
}

__device__ __forceinline__ int edge_count(int is64, int nwords) {
    if (is64) return (nwords >= 3000000) ? (nwords >> 2) : (nwords >> 1);
    return nwords >> 1;
}
__device__ __forceinline__ void load_edge(const void* raw, int is64, int e,
                                          int& s, int& d) {
    if (is64) {
        const long long* p = (const long long*)raw;
        s = (int)p[2 * (long long)e];
        d = (int)p[2 * (long long)e + 1];
    } else {
        const int* p = (const int*)raw;
        s = p[2 * e];
        d = p[2 * e + 1];
    }
}

// ---------------------------------------------------------------------------
// Kernel 0: detect edge dtype + zero per-node counters
// ---------------------------------------------------------------------------
__global__ void detect_dtype_kernel(const int* __restrict__ w, int nwords) {
    __shared__ int any_nonzero;
    if (threadIdx.x == 0) any_nonzero = 0;
    __syncthreads();
    int limit = nwords / 2;
    if (limit > 16384) limit = 16384;
    for (int i = threadIdx.x; i < limit; i += blockDim.x) {
        if (w[2 * i + 1] != 0) any_nonzero = 1;
    }
    __syncthreads();
    if (threadIdx.x == 0) g_is64 = (any_nonzero == 0) ? 1 : 0;
    for (int i = threadIdx.x; i < NNODES; i += blockDim.x) g_cursor[i] = 0;
}

// ---------------------------------------------------------------------------
// Kernel 1: per-dst degree histogram
// ---------------------------------------------------------------------------
__global__ void count_kernel(const void* __restrict__ edges, int nwords) {
    int is64 = g_is64;
    int n = edge_count(is64, nwords);
    int e = blockIdx.x * blockDim.x + threadIdx.x;
    if (e >= n) return;
    int s, d;
    load_edge(edges, is64, e, s, d);
    atomicAdd(&g_cursor[d], 1);
}

// ---------------------------------------------------------------------------
// Kernel 2: exclusive scan -> row_start; reset cursors
// ---------------------------------------------------------------------------
__global__ void scan_kernel() {
    __shared__ int part[1024];
    int t = threadIdx.x;
    const int chunk = (NNODES + 1023) / 1024;   // 49
    int begin = t * chunk;
    int end = begin + chunk;
    if (end > NNODES) end = NNODES;
    int s = 0;
    for (int i = begin; i < end; i++) s += g_cursor[i];
    part[t] = s;
    __syncthreads();
    for (int off = 1; off < 1024; off <<= 1) {
        int v = (t >= off) ? part[t - off] : 0;
        __syncthreads();
        part[t] += v;
        __syncthreads();
    }
    int offset = (t > 0) ? part[t - 1] : 0;
    for (int i = begin; i < end; i++) {
        int c = g_cursor[i];
        g_row_start[i] = offset;
        offset += c;
        g_cursor[i] = 0;
    }
    if (t == 1023) g_row_start[NNODES] = part[1023];
}

// ---------------------------------------------------------------------------
// Kernel 3: fill CSR column (src) lists
// ---------------------------------------------------------------------------
__global__ void fill_kernel(const void* __restrict__ edges, int nwords) {
    int is64 = g_is64;
    int n = edge_count(is64, nwords);
    int e = blockIdx.x * blockDim.x + threadIdx.x;
    if (e >= n) return;
    int s, d;
    load_edge(edges, is64, e, s, d);
    int pos = g_row_start[d] + atomicAdd(&g_cursor[d], 1);
    g_col[pos] = s;
}

// ---------------------------------------------------------------------------
// Kernel 4: fused gather + dual-GEMM + bias + ReLU.
// Block = 256 threads (8 warps), 128 rows.
//  Phase A: stage x-tile + weights.
//  Phase B: gather — HALF-WARP per row (lane-in-half owns one float4),
//           two rows concurrently per warp; 4-deep unrolled edge loads
//           (warp in-flight = 2KB) to reach the LTS bandwidth cap.
//  Phase C: f32x2 GEMM (unchanged from R5 shape).
// ---------------------------------------------------------------------------
#define WSTRIDE 68
#define SX_OFF 0
#define SA_OFF (128 * 64)
#define SWS_OFF (2 * 128 * 64)
#define SWN_OFF (SWS_OFF + 64 * WSTRIDE)
#define SB_OFF (SWN_OFF + 64 * WSTRIDE)
#define SMEM_FLOATS (SB_OFF + 64)

__global__ __launch_bounds__(256) void fused_gnn_kernel(
        const float* __restrict__ x,
        const float* __restrict__ Ws, const float* __restrict__ bs,
        const float* __restrict__ Wn, const float* __restrict__ bn,
        float* __restrict__ out) {
    extern __shared__ float sm[];
    float* sX = sm + SX_OFF;
    float* sA = sm + SA_OFF;
    float* sWs = sm + SWS_OFF;
    float* sWn = sm + SWN_OFF;
    float* sb = sm + SB_OFF;

    int tid = threadIdx.x;
    int warp = tid >> 5;
    int lane = tid & 31;
    int h = lane >> 4;        // half-warp id
    int li = lane & 15;       // lane within half
    size_t rowbase = (size_t)blockIdx.x * 128;

    // --- Phase A: stage x rows + weights ---
    {
        const float4* xg = reinterpret_cast<const float4*>(x + rowbase * DIM);
        float4* sx4 = reinterpret_cast<float4*>(sX);
#pragma unroll
        for (int t = 0; t < 8; t++) {
            int idx = tid + t * 256;
            sx4[idx] = xg[idx];
        }
    }
    for (int idx = tid; idx < DIM * DIM; idx += 256) {
        int o = idx >> 6;
        int k = idx & 63;
        sWs[k * WSTRIDE + o] = Ws[idx];
        sWn[k * WSTRIDE + o] = Wn[idx];
    }
    if (tid < DIM) sb[tid] = bs[tid] + bn[tid];

    // --- Phase B: gather agg rows into sA (half-warp per row) ---
    unsigned hmask = 0xFFFFu << (16 * h);
#pragma unroll 1
    for (int pr = 0; pr < 8; pr++) {
        int rl = warp * 16 + 2 * pr + h;
        size_t row = rowbase + (size_t)rl;
        int b = (int)(row / NNODES);
        int node = (int)(row % NNODES);
        int start = g_row_start[node];
        int end = g_row_start[node + 1];
        const float* xb = x + (size_t)b * NNODES * DIM;

        float4 a0 = {0.f, 0.f, 0.f, 0.f};
        float4 a1 = {0.f, 0.f, 0.f, 0.f};
        float4 a2 = {0.f, 0.f, 0.f, 0.f};
        float4 a3 = {0.f, 0.f, 0.f, 0.f};

        for (int e0 = start; e0 < end; e0 += 16) {
            int cnt = end - e0;
            if (cnt > 16) cnt = 16;
            int my = (li < cnt) ? g_col[e0 + li] : 0;
            int t = 0;
            for (; t + 4 <= cnt; t += 4) {
                int s0 = __shfl_sync(hmask, my, t, 16);
                int s1 = __shfl_sync(hmask, my, t + 1, 16);
                int s2 = __shfl_sync(hmask, my, t + 2, 16);
                int s3 = __shfl_sync(hmask, my, t + 3, 16);
                float4 v0 = *reinterpret_cast<const float4*>(xb + (size_t)s0 * DIM + 4 * li);
                float4 v1 = *reinterpret_cast<const float4*>(xb + (size_t)s1 * DIM + 4 * li);
                float4 v2 = *reinterpret_cast<const float4*>(xb + (size_t)s2 * DIM + 4 * li);
                float4 v3 = *reinterpret_cast<const float4*>(xb + (size_t)s3 * DIM + 4 * li);
                a0.x += v0.x; a0.y += v0.y; a0.z += v0.z; a0.w += v0.w;
                a1.x += v1.x; a1.y += v1.y; a1.z += v1.z; a1.w += v1.w;
                a2.x += v2.x; a2.y += v2.y; a2.z += v2.z; a2.w += v2.w;
                a3.x += v3.x; a3.y += v3.y; a3.z += v3.z; a3.w += v3.w;
            }
            for (; t < cnt; t++) {
                int s0 = __shfl_sync(hmask, my, t, 16);
                float4 v0 = *reinterpret_cast<const float4*>(xb + (size_t)s0 * DIM + 4 * li);
                a0.x += v0.x; a0.y += v0.y; a0.z += v0.z; a0.w += v0.w;
            }
        }
        float4 s;
        s.x = (a0.x + a1.x) + (a2.x + a3.x);
        s.y = (a0.y + a1.y) + (a2.y + a3.y);
        s.z = (a0.z + a1.z) + (a2.z + a3.z);
        s.w = (a0.w + a1.w) + (a2.w + a3.w);
        *reinterpret_cast<float4*>(&sA[rl * DIM + 4 * li]) = s;
    }
    __syncthreads();

    // --- Phase C: GEMM + bias + relu ---
    int i = li;   // output group: outputs 4i..4i+3

    unsigned long long bias0 = pack2(sb[4 * i], sb[4 * i + 1]);
    unsigned long long bias1 = pack2(sb[4 * i + 2], sb[4 * i + 3]);
    unsigned long long acc[8][2];
#pragma unroll
    for (int j = 0; j < 8; j++) { acc[j][0] = bias0; acc[j][1] = bias1; }

    int row0 = warp * 16 + h;

#pragma unroll 1
    for (int c = 0; c < 16; c++) {
        int k0 = c * 4;
        unsigned long long wsv[4][2], wnv[4][2];
#pragma unroll
        for (int k = 0; k < 4; k++) {
            float4 w = *reinterpret_cast<const float4*>(&sWs[(k0 + k) * WSTRIDE + 4 * i]);
            wsv[k][0] = pack2(w.x, w.y);
            wsv[k][1] = pack2(w.z, w.w);
            float4 u = *reinterpret_cast<const float4*>(&sWn[(k0 + k) * WSTRIDE + 4 * i]);
            wnv[k][0] = pack2(u.x, u.y);
            wnv[k][1] = pack2(u.z, u.w);
        }
#pragma unroll
        for (int j = 0; j < 8; j++) {
            int r = row0 + 2 * j;
            float4 xv = *reinterpret_cast<const float4*>(&sX[r * DIM + k0]);
            float4 av = *reinterpret_cast<const float4*>(&sA[r * DIM + k0]);
            float xe[4] = {xv.x, xv.y, xv.z, xv.w};
            float ae[4] = {av.x, av.y, av.z, av.w};
#pragma unroll
            for (int k = 0; k < 4; k++) {
                unsigned long long xp = pack2(xe[k], xe[k]);
                unsigned long long ap = pack2(ae[k], ae[k]);
                acc[j][0] = fma2(xp, wsv[k][0], acc[j][0]);
                acc[j][0] = fma2(ap, wnv[k][0], acc[j][0]);
                acc[j][1] = fma2(xp, wsv[k][1], acc[j][1]);
                acc[j][1] = fma2(ap, wnv[k][1], acc[j][1]);
            }
        }
    }

#pragma unroll
    for (int j = 0; j < 8; j++) {
        size_t row = rowbase + (size_t)(row0 + 2 * j);
        float l0, h0, l1, h1;
        unpack2(acc[j][0], l0, h0);
        unpack2(acc[j][1], l1, h1);
        float4 r;
        r.x = fmaxf(l0, 0.f);
        r.y = fmaxf(h0, 0.f);
        r.z = fmaxf(l1, 0.f);
        r.w = fmaxf(h1, 0.f);
        *reinterpret_cast<float4*>(out + row * DIM + 4 * i) = r;
    }
}

// ---------------------------------------------------------------------------
// Launch
// ---------------------------------------------------------------------------
extern "C" void kernel_launch(void* const* d_in, const int* in_sizes, int n_in,
                              void* d_out, int out_size) {
    const float* x = (const float*)d_in[0];
    const void* edges = d_in[1];
    const float* Ws = (const float*)d_in[2];
    const float* bs = (const float*)d_in[3];
    const float* Wn = (const float*)d_in[4];
    const float* bn = (const float*)d_in[5];
    float* out = (float*)d_out;

    int nwords = in_sizes[1];
    int max_edges = nwords / 2;
    int eblocks = (max_edges + 255) / 256;

    // CSR build
    detect_dtype_kernel<<<1, 256>>>((const int*)edges, nwords);
    count_kernel<<<eblocks, 256>>>(edges, nwords);
    scan_kernel<<<1, 1024>>>();
    fill_kernel<<<eblocks, 256>>>(edges, nwords);

    // fused gather + dual-GEMM + relu
    int smem_bytes = SMEM_FLOATS * (int)sizeof(float);
    cudaFuncSetAttribute(fused_gnn_kernel,
                         cudaFuncAttributeMaxDynamicSharedMemorySize, smem_bytes);
    int gblocks = (int)(TOTAL_ROWS / 128);   // 3125
    fused_gnn_kernel<<<gblocks, 256, smem_bytes>>>(x, Ws, bs, Wn, bn, out);
}

// round 13
// speedup vs baseline: 1.1828x; 1.0216x over previous
#include <cuda_runtime.h>
#include <cstdint>

#define BATCH 8
#define NNODES 50000
#define DIM 64
#define ROW_F4 16
#define TOTAL_ROWS ((size_t)BATCH * NNODES)   // 400000
#define MAX_E 1600000

__device__ float4 g_agg[TOTAL_ROWS * ROW_F4];   // 102.4 MB, 16B-aligned
__device__ int g_is64;
__device__ int g_row_start[NNODES + 1];
__device__ int g_cursor[NNODES];
__device__ int g_col[MAX_E];

// ---------------------------------------------------------------------------
// packed f32x2 helpers
// ---------------------------------------------------------------------------
__device__ __forceinline__ unsigned long long pack2(float a, float b) {
    unsigned long long r;
    asm("mov.b64 %0, {%1, %2};" : "=l"(r) : "f"(a), "f"(b));
    return r;
}
__device__ __forceinline__ unsigned long long fma2(unsigned long long a,
                                                   unsigned long long b,
                                                   unsigned long long c) {
    unsigned long long d;
    asm("fma.rn.f32x2 %0, %1, %2, %3;" : "=l"(d) : "l"(a), "l"(b), "l"(c));
    return d;
}
__device__ __forceinline__ void unpack2(unsigned long long v, float& lo, float& hi) {
    asm("mov.b64 {%0, %1}, %2;" : "=f"(lo), "=f"(hi) : "l"(v));
}

__device__ __forceinline__ int edge_count(int is64, int nwords) {
    if (is64) return (nwords >= 3000000) ? (nwords >> 2) : (nwords >> 1);
    return nwords >> 1;
}
__device__ __forceinline__ void load_edge(const void* raw, int is64, int e,
                                          int& s, int& d) {
    if (is64) {
        const long long* p = (const long long*)raw;
        s = (int)p[2 * (long long)e];
        d = (int)p[2 * (long long)e + 1];
    } else {
        const int* p = (const int*)raw;
        s = p[2 * e];
        d = p[2 * e + 1];
    }
}

// ---------------------------------------------------------------------------
// Kernel 0: detect edge dtype + zero per-node counters
// ---------------------------------------------------------------------------
__global__ void detect_dtype_kernel(const int* __restrict__ w, int nwords) {
    __shared__ int any_nonzero;
    if (threadIdx.x == 0) any_nonzero = 0;
    __syncthreads();
    int limit = nwords / 2;
    if (limit > 16384) limit = 16384;
    for (int i = threadIdx.x; i < limit; i += blockDim.x) {
        if (w[2 * i + 1] != 0) any_nonzero = 1;
    }
    __syncthreads();
    if (threadIdx.x == 0) g_is64 = (any_nonzero == 0) ? 1 : 0;
    for (int i = threadIdx.x; i < NNODES; i += blockDim.x) g_cursor[i] = 0;
}

// ---------------------------------------------------------------------------
// Kernel 1: per-dst degree histogram
// ---------------------------------------------------------------------------
__global__ void count_kernel(const void* __restrict__ edges, int nwords) {
    int is64 = g_is64;
    int n = edge_count(is64, nwords);
    int e = blockIdx.x * blockDim.x + threadIdx.x;
    if (e >= n) return;
    int s, d;
    load_edge(edges, is64, e, s, d);
    atomicAdd(&g_cursor[d], 1);
}

// ---------------------------------------------------------------------------
// Kernel 2: exclusive scan -> row_start; reset cursors
// ---------------------------------------------------------------------------
__global__ void scan_kernel() {
    __shared__ int part[1024];
    int t = threadIdx.x;
    const int chunk = (NNODES + 1023) / 1024;   // 49
    int begin = t * chunk;
    int end = begin + chunk;
    if (end > NNODES) end = NNODES;
    int s = 0;
    for (int i = begin; i < end; i++) s += g_cursor[i];
    part[t] = s;
    __syncthreads();
    for (int off = 1; off < 1024; off <<= 1) {
        int v = (t >= off) ? part[t - off] : 0;
        __syncthreads();
        part[t] += v;
        __syncthreads();
    }
    int offset = (t > 0) ? part[t - 1] : 0;
    for (int i = begin; i < end; i++) {
        int c = g_cursor[i];
        g_row_start[i] = offset;
        offset += c;
        g_cursor[i] = 0;
    }
    if (t == 1023) g_row_start[NNODES] = part[1023];
}

// ---------------------------------------------------------------------------
// Kernel 3: fill CSR column (src) lists
// ---------------------------------------------------------------------------
__global__ void fill_kernel(const void* __restrict__ edges, int nwords) {
    int is64 = g_is64;
    int n = edge_count(is64, nwords);
    int e = blockIdx.x * blockDim.x + threadIdx.x;
    if (e >= n) return;
    int s, d;
    load_edge(edges, is64, e, s, d);
    int pos = g_row_start[d] + atomicAdd(&g_cursor[d], 1);
    g_col[pos] = s;
}

// ---------------------------------------------------------------------------
// Kernel 4: CSR gather. ONE WARP PER NODE, all 8 batches at once.
// Lane l owns (batch b = l>>2, 64B chunk q = l&3): 4 contiguous float4 of
// x[b][src]. Edges unrolled 2-deep -> 8 independent LDG.128 per lane in
// flight (4KB/warp). Also writes zeros for degree-0 nodes (no zero pass).
// ---------------------------------------------------------------------------
__global__ __launch_bounds__(256) void gather_kernel(const float* __restrict__ x) {
    int node = (int)((blockIdx.x * (size_t)blockDim.x + threadIdx.x) >> 5);
    if (node >= NNODES) return;
    int lane = threadIdx.x & 31;
    int b = lane >> 2;          // batch 0..7
    int q = lane & 3;           // 64B chunk: float4 indices 4q..4q+3

    int start = g_row_start[node];
    int end = g_row_start[node + 1];

    const float4* xb = reinterpret_cast<const float4*>(x) +
                       (size_t)b * NNODES * ROW_F4 + 4 * q;

    float4 aA0 = {0,0,0,0}, aA1 = {0,0,0,0}, aA2 = {0,0,0,0}, aA3 = {0,0,0,0};
    float4 aB0 = {0,0,0,0}, aB1 = {0,0,0,0}, aB2 = {0,0,0,0}, aB3 = {0,0,0,0};

    for (int e0 = start; e0 < end; e0 += 32) {
        int cnt = end - e0;
        if (cnt > 32) cnt = 32;
        int my = (lane < cnt) ? g_col[e0 + lane] : 0;
        int t = 0;
        for (; t + 2 <= cnt; t += 2) {
            int s0 = __shfl_sync(0xffffffffu, my, t);
            int s1 = __shfl_sync(0xffffffffu, my, t + 1);
            const float4* p0 = xb + (size_t)s0 * ROW_F4;
            const float4* p1 = xb + (size_t)s1 * ROW_F4;
            float4 v00 = p0[0], v01 = p0[1], v02 = p0[2], v03 = p0[3];
            float4 v10 = p1[0], v11 = p1[1], v12 = p1[2], v13 = p1[3];
            aA0.x += v00.x; aA0.y += v00.y; aA0.z += v00.z; aA0.w += v00.w;
            aA1.x += v01.x; aA1.y += v01.y; aA1.z += v01.z; aA1.w += v01.w;
            aA2.x += v02.x; aA2.y += v02.y; aA2.z += v02.z; aA2.w += v02.w;
            aA3.x += v03.x; aA3.y += v03.y; aA3.z += v03.z; aA3.w += v03.w;
            aB0.x += v10.x; aB0.y += v10.y; aB0.z += v10.z; aB0.w += v10.w;
            aB1.x += v11.x; aB1.y += v11.y; aB1.z += v11.z; aB1.w += v11.w;
            aB2.x += v12.x; aB2.y += v12.y; aB2.z += v12.z; aB2.w += v12.w;
            aB3.x += v13.x; aB3.y += v13.y; aB3.z += v13.z; aB3.w += v13.w;
        }
        if (t < cnt) {
            int s0 = __shfl_sync(0xffffffffu, my, t);
            const float4* p0 = xb + (size_t)s0 * ROW_F4;
            float4 v00 = p0[0], v01 = p0[1], v02 = p0[2], v03 = p0[3];
            aA0.x += v00.x; aA0.y += v00.y; aA0.z += v00.z; aA0.w += v00.w;
            aA1.x += v01.x; aA1.y += v01.y; aA1.z += v01.z; aA1.w += v01.w;
            aA2.x += v02.x; aA2.y += v02.y; aA2.z += v02.z; aA2.w += v02.w;
            aA3.x += v03.x; aA3.y += v03.y; aA3.z += v03.z; aA3.w += v03.w;
        }
    }

    float4* dst = &g_agg[((size_t)b * NNODES + (size_t)node) * ROW_F4 + 4 * q];
    float4 r0, r1, r2, r3;
    r0.x = aA0.x + aB0.x; r0.y = aA0.y + aB0.y; r0.z = aA0.z + aB0.z; r0.w = aA0.w + aB0.w;
    r1.x = aA1.x + aB1.x; r1.y = aA1.y + aB1.y; r1.z = aA1.z + aB1.z; r1.w = aA1.w + aB1.w;
    r2.x = aA2.x + aB2.x; r2.y = aA2.y + aB2.y; r2.z = aA2.z + aB2.z; r2.w = aA2.w + aB2.w;
    r3.x = aA3.x + aB3.x; r3.y = aA3.y + aB3.y; r3.z = aA3.z + aB3.z; r3.w = aA3.w + aB3.w;
    dst[0] = r0; dst[1] = r1; dst[2] = r2; dst[3] = r3;
}

// ---------------------------------------------------------------------------
// Kernel 5: dual-GEMM + bias + ReLU (proven R5 shape, 177us).
// Block = 256 threads, 128 rows; smem-staged x/agg; f32x2 FMA.
// ---------------------------------------------------------------------------
#define WSTRIDE 68
#define SX_OFF 0
#define SA_OFF (128 * 64)
#define SWS_OFF (2 * 128 * 64)
#define SWN_OFF (SWS_OFF + 64 * WSTRIDE)
#define SB_OFF (SWN_OFF + 64 * WSTRIDE)
#define SMEM_FLOATS (SB_OFF + 64)

__global__ __launch_bounds__(256) void gemm_relu_kernel(
        const float* __restrict__ x,
        const float* __restrict__ Ws, const float* __restrict__ bs,
        const float* __restrict__ Wn, const float* __restrict__ bn,
        float* __restrict__ out) {
    extern __shared__ float sm[];
    float* sX = sm + SX_OFF;
    float* sA = sm + SA_OFF;
    float* sWs = sm + SWS_OFF;
    float* sWn = sm + SWN_OFF;
    float* sb = sm + SB_OFF;

    int tid = threadIdx.x;
    size_t rowbase = (size_t)blockIdx.x * 128;

    {
        const float4* xg = reinterpret_cast<const float4*>(x + rowbase * DIM);
        const float4* ag = &g_agg[rowbase * ROW_F4];
        float4* sx4 = reinterpret_cast<float4*>(sX);
        float4* sa4 = reinterpret_cast<float4*>(sA);
#pragma unroll
        for (int t = 0; t < 8; t++) {
            int idx = tid + t * 256;
            sx4[idx] = xg[idx];
            sa4[idx] = ag[idx];
        }
    }
    for (int idx = tid; idx < DIM * DIM; idx += 256) {
        int o = idx >> 6;
        int k = idx & 63;
        sWs[k * WSTRIDE + o] = Ws[idx];
        sWn[k * WSTRIDE + o] = Wn[idx];
    }
    if (tid < DIM) sb[tid] = bs[tid] + bn[tid];
    __syncthreads();

    int warp = tid >> 5;
    int lane = tid & 31;
    int h = lane >> 4;
    int i = lane & 15;

    unsigned long long bias0 = pack2(sb[4 * i], sb[4 * i + 1]);
    unsigned long long bias1 = pack2(sb[4 * i + 2], sb[4 * i + 3]);
    unsigned long long acc[8][2];
#pragma unroll
    for (int j = 0; j < 8; j++) { acc[j][0] = bias0; acc[j][1] = bias1; }

    int row0 = warp * 16 + h;

#pragma unroll 1
    for (int c = 0; c < 16; c++) {
        int k0 = c * 4;
        unsigned long long wsv[4][2], wnv[4][2];
#pragma unroll
        for (int k = 0; k < 4; k++) {
            float4 w = *reinterpret_cast<const float4*>(&sWs[(k0 + k) * WSTRIDE + 4 * i]);
            wsv[k][0] = pack2(w.x, w.y);
            wsv[k][1] = pack2(w.z, w.w);
            float4 u = *reinterpret_cast<const float4*>(&sWn[(k0 + k) * WSTRIDE + 4 * i]);
            wnv[k][0] = pack2(u.x, u.y);
            wnv[k][1] = pack2(u.z, u.w);
        }
#pragma unroll
        for (int j = 0; j < 8; j++) {
            int r = row0 + 2 * j;
            float4 xv = *reinterpret_cast<const float4*>(&sX[r * DIM + k0]);
            float4 av = *reinterpret_cast<const float4*>(&sA[r * DIM + k0]);
            float xe[4] = {xv.x, xv.y, xv.z, xv.w};
            float ae[4] = {av.x, av.y, av.z, av.w};
#pragma unroll
            for (int k = 0; k < 4; k++) {
                unsigned long long xp = pack2(xe[k], xe[k]);
                unsigned long long ap = pack2(ae[k], ae[k]);
                acc[j][0] = fma2(xp, wsv[k][0], acc[j][0]);
                acc[j][0] = fma2(ap, wnv[k][0], acc[j][0]);
                acc[j][1] = fma2(xp, wsv[k][1], acc[j][1]);
                acc[j][1] = fma2(ap, wnv[k][1], acc[j][1]);
            }
        }
    }

#pragma unroll
    for (int j = 0; j < 8; j++) {
        size_t row = rowbase + (size_t)(row0 + 2 * j);
        float l0, h0, l1, h1;
        unpack2(acc[j][0], l0, h0);
        unpack2(acc[j][1], l1, h1);
        float4 r;
        r.x = fmaxf(l0, 0.f);
        r.y = fmaxf(h0, 0.f);
        r.z = fmaxf(l1, 0.f);
        r.w = fmaxf(h1, 0.f);
        *reinterpret_cast<float4*>(out + row * DIM + 4 * i) = r;
    }
}

// ---------------------------------------------------------------------------
// Launch
// ---------------------------------------------------------------------------
extern "C" void kernel_launch(void* const* d_in, const int* in_sizes, int n_in,
                              void* d_out, int out_size) {
    const float* x = (const float*)d_in[0];
    const void* edges = d_in[1];
    const float* Ws = (const float*)d_in[2];
    const float* bs = (const float*)d_in[3];
    const float* Wn = (const float*)d_in[4];
    const float* bn = (const float*)d_in[5];
    float* out = (float*)d_out;

    int nwords = in_sizes[1];
    int max_edges = nwords / 2;
    int eblocks = (max_edges + 255) / 256;

    // CSR build
    detect_dtype_kernel<<<1, 256>>>((const int*)edges, nwords);
    count_kernel<<<eblocks, 256>>>(edges, nwords);
    scan_kernel<<<1, 1024>>>();
    fill_kernel<<<eblocks, 256>>>(edges, nwords);

    // gather: one warp per node (all batches), 8 warps per block
    gather_kernel<<<(NNODES + 7) / 8, 256>>>(x);

    // dual-GEMM + bias + relu
    int smem_bytes = SMEM_FLOATS * (int)sizeof(float);
    cudaFuncSetAttribute(gemm_relu_kernel,
                         cudaFuncAttributeMaxDynamicSharedMemorySize, smem_bytes);
    int gblocks = (int)(TOTAL_ROWS / 128);   // 3125
    gemm_relu_kernel<<<gblocks, 256, smem_bytes>>>(x, Ws, bs, Wn, bn, out);
}